// round 1
// baseline (speedup 1.0000x reference)
#include <cuda_runtime.h>

// ApproximateConv2d: z[b,o,h,w] = mu_w * sum_{c,kh,kw} min(x_pad, w)
// x: (4,32,56,56) f32, w: (64,32,3,3) f32, out: (4,64,56,56) f32

#define Bn 4
#define Cn 32
#define Hn 56
#define Wn 56
#define On 64
#define KK 9
#define CKK 288           // C*K*K

#define TO 16             // output channels per thread
#define OG (On / TO)      // 4 o-groups
#define TH 4              // output rows per block
#define NBAND (Hn / TH)   // 14
#define THREADS (TH * Wn) // 224

#define CCHUNK 8
#define NCHUNK (Cn / CCHUNK) // 4
#define XS_ROWS (TH + 2)     // 6
#define XS_COLS (Wn + 2)     // 58
#define XS_SIZE (CCHUNK * XS_ROWS * XS_COLS)

__device__ float g_mu;

// ---------------------------------------------------------------------------
// mu_w = mean(|w|) over all 18432 weights — single-block reduction
// ---------------------------------------------------------------------------
__global__ void mu_kernel(const float* __restrict__ w) {
    __shared__ float red[256];
    const int n4 = (On * CKK) / 4; // 4608
    const float4* w4 = reinterpret_cast<const float4*>(w);
    float s = 0.f;
    for (int i = threadIdx.x; i < n4; i += 256) {
        float4 v = w4[i];
        s += fabsf(v.x) + fabsf(v.y) + fabsf(v.z) + fabsf(v.w);
    }
    red[threadIdx.x] = s;
    __syncthreads();
    for (int off = 128; off > 0; off >>= 1) {
        if (threadIdx.x < off) red[threadIdx.x] += red[threadIdx.x + off];
        __syncthreads();
    }
    if (threadIdx.x == 0) g_mu = red[0] / (float)(On * CKK);
}

// ---------------------------------------------------------------------------
// Main kernel.
// grid = (OG, NBAND, Bn); block = 224 threads (thread = one output pixel in a
// 4x56 band), each thread accumulates TO=16 output channels.
// ---------------------------------------------------------------------------
__global__ __launch_bounds__(THREADS)
void approx_conv_kernel(const float* __restrict__ x,
                        const float* __restrict__ w,
                        float* __restrict__ out) {
    __shared__ __align__(16) float ws[CKK * TO];  // 18432 B
    __shared__ float xs[XS_SIZE];                 // 11136 B

    const int tid   = threadIdx.x;
    const int og    = blockIdx.x;
    const int band  = blockIdx.y;
    const int b     = blockIdx.z;
    const int obase = og * TO;
    const int hbase = band * TH;

    // Load weights for this o-group: ws[ck*TO + oo] = w[(obase+oo)*CKK + ck]
    for (int i = tid; i < CKK * TO; i += THREADS) {
        int ck = i / TO;
        int oo = i % TO;
        ws[i] = w[(obase + oo) * CKK + ck];
    }

    const int row = tid / Wn;  // 0..3
    const int col = tid % Wn;  // 0..55

    float acc[TO];
#pragma unroll
    for (int i = 0; i < TO; i++) acc[i] = 0.f;

    for (int ch = 0; ch < NCHUNK; ch++) {
        __syncthreads();
        // Load x chunk (8 channels, padded 6x58 rows, zero outside image)
        for (int i = tid; i < XS_SIZE; i += THREADS) {
            int cc  = i / (XS_ROWS * XS_COLS);
            int rem = i % (XS_ROWS * XS_COLS);
            int r   = rem / XS_COLS;
            int cl  = rem % XS_COLS;
            int gh  = hbase + r - 1;
            int gw  = cl - 1;
            float v = 0.f;
            if (gh >= 0 && gh < Hn && gw >= 0 && gw < Wn)
                v = x[((b * Cn + ch * CCHUNK + cc) * Hn + gh) * Wn + gw];
            xs[i] = v;
        }
        __syncthreads();

#pragma unroll 2
        for (int cc = 0; cc < CCHUNK; cc++) {
            const int   ckbase = (ch * CCHUNK + cc) * KK;
            const float* xbase = &xs[cc * (XS_ROWS * XS_COLS) + row * XS_COLS + col];
#pragma unroll
            for (int kh = 0; kh < 3; kh++) {
#pragma unroll
                for (int kw = 0; kw < 3; kw++) {
                    float xv = xbase[kh * XS_COLS + kw];
                    const float4* wp4 = reinterpret_cast<const float4*>(
                        &ws[(ckbase + kh * 3 + kw) * TO]);
                    float4 w0 = wp4[0];
                    float4 w1 = wp4[1];
                    float4 w2 = wp4[2];
                    float4 w3 = wp4[3];
                    acc[0]  += fminf(xv, w0.x);
                    acc[1]  += fminf(xv, w0.y);
                    acc[2]  += fminf(xv, w0.z);
                    acc[3]  += fminf(xv, w0.w);
                    acc[4]  += fminf(xv, w1.x);
                    acc[5]  += fminf(xv, w1.y);
                    acc[6]  += fminf(xv, w1.z);
                    acc[7]  += fminf(xv, w1.w);
                    acc[8]  += fminf(xv, w2.x);
                    acc[9]  += fminf(xv, w2.y);
                    acc[10] += fminf(xv, w2.z);
                    acc[11] += fminf(xv, w2.w);
                    acc[12] += fminf(xv, w3.x);
                    acc[13] += fminf(xv, w3.y);
                    acc[14] += fminf(xv, w3.z);
                    acc[15] += fminf(xv, w3.w);
                }
            }
        }
    }

    const float mu = g_mu;
    const int h = hbase + row;
#pragma unroll
    for (int oo = 0; oo < TO; oo++) {
        out[((b * On + obase + oo) * Hn + h) * Wn + col] = mu * acc[oo];
    }
}

extern "C" void kernel_launch(void* const* d_in, const int* in_sizes, int n_in,
                              void* d_out, int out_size) {
    const float* x = (const float*)d_in[0];
    const float* w = (const float*)d_in[1];
    float* out = (float*)d_out;

    mu_kernel<<<1, 256>>>(w);

    dim3 grid(OG, NBAND, Bn);
    approx_conv_kernel<<<grid, THREADS>>>(x, w, out);
}

// round 2
// speedup vs baseline: 1.2600x; 1.2600x over previous
#include <cuda_runtime.h>

// ApproximateConv2d: z[b,o,h,w] = mu_w * sum_{c,kh,kw} min(x_pad, w)
// x: (4,32,56,56) f32, w: (64,32,3,3) f32, out: (4,64,56,56) f32

#define Bn 4
#define Cn 32
#define Hn 56
#define Wn 56
#define On 64
#define KK 9
#define CKK 288           // C*K*K

#define TO 8              // output channels per thread
#define OG (On / TO)      // 8 o-groups
#define TH 4              // output rows per block
#define NBAND (Hn / TH)   // 14
#define THREADS (TH * Wn) // 224

#define CCHUNK 16
#define NCHUNK (Cn / CCHUNK) // 2
#define XS_ROWS (TH + 2)     // 6
#define XS_COLS (Wn + 2)     // 58
#define XS_PLANE (XS_ROWS * XS_COLS)
#define XS_SIZE (CCHUNK * XS_PLANE)

__device__ float g_mu;

// ---------------------------------------------------------------------------
// mu_w = mean(|w|) over all 18432 weights — single-block reduction
// ---------------------------------------------------------------------------
__global__ void mu_kernel(const float* __restrict__ w) {
    __shared__ float red[256];
    const int n4 = (On * CKK) / 4; // 4608
    const float4* w4 = reinterpret_cast<const float4*>(w);
    float s = 0.f;
    for (int i = threadIdx.x; i < n4; i += 256) {
        float4 v = w4[i];
        s += fabsf(v.x) + fabsf(v.y) + fabsf(v.z) + fabsf(v.w);
    }
    red[threadIdx.x] = s;
    __syncthreads();
    for (int off = 128; off > 0; off >>= 1) {
        if (threadIdx.x < off) red[threadIdx.x] += red[threadIdx.x + off];
        __syncthreads();
    }
    if (threadIdx.x == 0) g_mu = red[0] / (float)(On * CKK);
}

// ---------------------------------------------------------------------------
// Main kernel.
// grid = (OG=8, NBAND=14, Bn=4) = 448 blocks (3.03 waves of 148 SMs).
// block = 224 threads; thread = one output pixel in a 4x56 band, TO=8 channels.
// ---------------------------------------------------------------------------
__global__ __launch_bounds__(THREADS)
void approx_conv_kernel(const float* __restrict__ x,
                        const float* __restrict__ w,
                        float* __restrict__ out) {
    __shared__ __align__(16) float ws[CKK * TO];  // 9216 B
    __shared__ float xs[XS_SIZE];                 // 22272 B

    const int tid   = threadIdx.x;
    const int og    = blockIdx.x;
    const int band  = blockIdx.y;
    const int b     = blockIdx.z;
    const int obase = og * TO;
    const int hbase = band * TH;

    // Load weights for this o-group: ws[ck*TO + oo] = w[(obase+oo)*CKK + ck]
    for (int i = tid; i < CKK * TO; i += THREADS) {
        int ck = i / TO;
        int oo = i % TO;
        ws[i] = w[(obase + oo) * CKK + ck];
    }

    const int row = tid / Wn;  // 0..3
    const int col = tid % Wn;  // 0..55

    float acc[TO];
#pragma unroll
    for (int i = 0; i < TO; i++) acc[i] = 0.f;

    for (int ch = 0; ch < NCHUNK; ch++) {
        __syncthreads();
        // Load x chunk (16 channels, padded 6x58 rows, zero outside image)
        for (int i = tid; i < XS_SIZE; i += THREADS) {
            int cc  = i / XS_PLANE;
            int rem = i % XS_PLANE;
            int r   = rem / XS_COLS;
            int cl  = rem % XS_COLS;
            int gh  = hbase + r - 1;
            int gw  = cl - 1;
            float v = 0.f;
            if (gh >= 0 && gh < Hn && gw >= 0 && gw < Wn)
                v = x[((b * Cn + ch * CCHUNK + cc) * Hn + gh) * Wn + gw];
            xs[i] = v;
        }
        __syncthreads();

#pragma unroll 2
        for (int cc = 0; cc < CCHUNK; cc++) {
            const int    ckbase = (ch * CCHUNK + cc) * KK;
            const float* xbase  = &xs[cc * XS_PLANE + row * XS_COLS + col];
#pragma unroll
            for (int kh = 0; kh < 3; kh++) {
#pragma unroll
                for (int kw = 0; kw < 3; kw++) {
                    float xv = xbase[kh * XS_COLS + kw];
                    const float4* wp4 = reinterpret_cast<const float4*>(
                        &ws[(ckbase + kh * 3 + kw) * TO]);
                    float4 w0 = wp4[0];
                    float4 w1 = wp4[1];
                    acc[0] += fminf(xv, w0.x);
                    acc[1] += fminf(xv, w0.y);
                    acc[2] += fminf(xv, w0.z);
                    acc[3] += fminf(xv, w0.w);
                    acc[4] += fminf(xv, w1.x);
                    acc[5] += fminf(xv, w1.y);
                    acc[6] += fminf(xv, w1.z);
                    acc[7] += fminf(xv, w1.w);
                }
            }
        }
    }

    const float mu = g_mu;
    const int h = hbase + row;
#pragma unroll
    for (int oo = 0; oo < TO; oo++) {
        out[((b * On + obase + oo) * Hn + h) * Wn + col] = mu * acc[oo];
    }
}

extern "C" void kernel_launch(void* const* d_in, const int* in_sizes, int n_in,
                              void* d_out, int out_size) {
    const float* x = (const float*)d_in[0];
    const float* w = (const float*)d_in[1];
    float* out = (float*)d_out;

    mu_kernel<<<1, 256>>>(w);

    dim3 grid(OG, NBAND, Bn);
    approx_conv_kernel<<<grid, THREADS>>>(x, w, out);
}